// round 2
// baseline (speedup 1.0000x reference)
#include <cuda_runtime.h>
#include <cstddef>

// Problem constants
#define BB 2
#define SS 2048
#define DM 1024
#define NH 16
#define HD 64
#define MROWS (BB*SS)          // 4096

// Scratch (device globals — no runtime allocation allowed)
__device__ float g_q[MROWS * DM];
__device__ float g_k[MROWS * DM];
__device__ float g_v[MROWS * DM];
__device__ float g_ctx[MROWS * DM];

// ---------------------------------------------------------------------------
// Tiled SGEMM: C[M,N] = A[M,K] @ W[K,N] (+bias). BM=BN=128, BK=16, 256 thr,
// 8x8 accumulators per thread. M=4096, N=K=1024 — all divisible, no bounds.
// ---------------------------------------------------------------------------
__device__ __forceinline__ void gemm_128x128(const float* __restrict__ A,
                                             const float* __restrict__ W,
                                             float* __restrict__ C,
                                             const float* __restrict__ bias,
                                             int K, int N)
{
    __shared__ float As[16][128];   // transposed A tile: As[k][m]
    __shared__ float Bs[16][128];

    const int tid = threadIdx.x;
    const int m0 = blockIdx.y * 128;
    const int n0 = blockIdx.x * 128;
    const int tr = tid >> 4;        // 0..15 -> rows tr*8..tr*8+7
    const int tc = tid & 15;        // 0..15 -> cols tc*8..tc*8+7

    float acc[8][8];
#pragma unroll
    for (int i = 0; i < 8; i++)
#pragma unroll
        for (int j = 0; j < 8; j++) acc[i][j] = 0.f;

    for (int k0 = 0; k0 < K; k0 += 16) {
        // Load A tile (128 rows x 16 cols) as float4, store transposed.
#pragma unroll
        for (int it = 0; it < 2; it++) {
            int f = tid + it * 256;          // 0..511 float4 slots
            int row = f >> 2;
            int c4  = (f & 3) << 2;
            float4 a = *(const float4*)&A[(size_t)(m0 + row) * K + k0 + c4];
            As[c4 + 0][row] = a.x;
            As[c4 + 1][row] = a.y;
            As[c4 + 2][row] = a.z;
            As[c4 + 3][row] = a.w;
        }
        // Load B tile (16 rows x 128 cols) as float4.
#pragma unroll
        for (int it = 0; it < 2; it++) {
            int f = tid + it * 256;
            int row = f >> 5;
            int c4  = (f & 31) << 2;
            *(float4*)&Bs[row][c4] =
                *(const float4*)&W[(size_t)(k0 + row) * N + n0 + c4];
        }
        __syncthreads();

#pragma unroll
        for (int kk = 0; kk < 16; kk++) {
            float a[8], b[8];
#pragma unroll
            for (int i = 0; i < 8; i++) a[i] = As[kk][tr * 8 + i];
#pragma unroll
            for (int j = 0; j < 8; j++) b[j] = Bs[kk][tc * 8 + j];
#pragma unroll
            for (int i = 0; i < 8; i++)
#pragma unroll
                for (int j = 0; j < 8; j++) acc[i][j] += a[i] * b[j];
        }
        __syncthreads();
    }

#pragma unroll
    for (int i = 0; i < 8; i++) {
        int row = m0 + tr * 8 + i;
#pragma unroll
        for (int j = 0; j < 8; j += 4) {
            int col = n0 + tc * 8 + j;
            float4 v;
            v.x = acc[i][j + 0];
            v.y = acc[i][j + 1];
            v.z = acc[i][j + 2];
            v.w = acc[i][j + 3];
            if (bias) {
                v.x += bias[col + 0];
                v.y += bias[col + 1];
                v.z += bias[col + 2];
                v.w += bias[col + 3];
            }
            *(float4*)&C[(size_t)row * N + col] = v;
        }
    }
}

// QKV projections: blockIdx.z in {0,1,2} selects (Wq->g_q, Wk->g_k, Wv->g_v)
__global__ void qkv_kernel(const float* __restrict__ X,
                           const float* __restrict__ Wq,
                           const float* __restrict__ Wk,
                           const float* __restrict__ Wv)
{
    const float* W;
    float* Out;
    if (blockIdx.z == 0)      { W = Wq; Out = g_q; }
    else if (blockIdx.z == 1) { W = Wk; Out = g_k; }
    else                      { W = Wv; Out = g_v; }
    gemm_128x128(X, W, Out, nullptr, DM, DM);
}

// Output projection: out = g_ctx @ Wo + bo
__global__ void proj_kernel(const float* __restrict__ Wo,
                            const float* __restrict__ bo,
                            float* __restrict__ out)
{
    gemm_128x128(g_ctx, Wo, out, bo, DM, DM);
}

// ---------------------------------------------------------------------------
// Flash-attention (fp32, causal). One block per (q-tile of 64, head, batch).
// 256 threads; S/P gemms use 4x4 per-thread subtiles; online softmax handled
// by 64 row-owner threads.
// ---------------------------------------------------------------------------
#define BQ 64
#define BKV 64
#define LDP 65   // padded row stride in shared

__global__ void attn_kernel()
{
    extern __shared__ float sm[];
    float* Qs = sm;                        // [64][65]
    float* Ks = Qs + BQ * LDP;             // [64][65]
    float* Vs = Ks + BKV * LDP;            // [64][65]
    float* Ps = Vs + BKV * LDP;            // [64][65] scores/probs
    __shared__ float m_sh[BQ], l_sh[BQ], alpha_sh[BQ];

    const int qt  = blockIdx.x;            // 0..31
    const int h   = blockIdx.y;            // 0..15
    const int b   = blockIdx.z;            // 0..1
    const int q0  = qt * BQ;
    const int tid = threadIdx.x;
    const int tr  = tid >> 4;              // 0..15 -> q rows tr*4..+3
    const int tc  = tid & 15;              // 0..15 -> cols   tc*4..+3
    const size_t base = (size_t)b * SS * DM + (size_t)h * HD;

    // Load Q tile
    for (int idx = tid; idx < BQ * HD; idx += 256) {
        int r = idx >> 6, d = idx & 63;
        Qs[r * LDP + d] = g_q[base + (size_t)(q0 + r) * DM + d];
    }
    if (tid < BQ) { m_sh[tid] = -1e30f; l_sh[tid] = 0.f; }

    float acc[4][4];
#pragma unroll
    for (int i = 0; i < 4; i++)
#pragma unroll
        for (int j = 0; j < 4; j++) acc[i][j] = 0.f;

    __syncthreads();

    const int nkt = qt + 1;                // causal: only tiles <= diagonal
    for (int kt = 0; kt < nkt; kt++) {
        const int k0 = kt * BKV;
        // Load K and V tiles
        for (int idx = tid; idx < BKV * HD; idx += 256) {
            int r = idx >> 6, d = idx & 63;
            size_t g = base + (size_t)(k0 + r) * DM + d;
            Ks[r * LDP + d] = g_k[g];
            Vs[r * LDP + d] = g_v[g];
        }
        __syncthreads();

        // S = Q @ K^T
        float s[4][4];
#pragma unroll
        for (int i = 0; i < 4; i++)
#pragma unroll
            for (int j = 0; j < 4; j++) s[i][j] = 0.f;

#pragma unroll 8
        for (int d = 0; d < HD; d++) {
            float a[4], kv[4];
#pragma unroll
            for (int i = 0; i < 4; i++) a[i]  = Qs[(tr * 4 + i) * LDP + d];
#pragma unroll
            for (int j = 0; j < 4; j++) kv[j] = Ks[(tc * 4 + j) * LDP + d];
#pragma unroll
            for (int i = 0; i < 4; i++)
#pragma unroll
                for (int j = 0; j < 4; j++) s[i][j] += a[i] * kv[j];
        }

        // scale + causal mask, write to shared
        const bool diag = (kt == qt);
#pragma unroll
        for (int i = 0; i < 4; i++) {
            int qi = q0 + tr * 4 + i;
#pragma unroll
            for (int j = 0; j < 4; j++) {
                int kj = k0 + tc * 4 + j;
                float v = (!diag || kj <= qi) ? s[i][j] * 0.125f : -1e30f;
                Ps[(tr * 4 + i) * LDP + (tc * 4 + j)] = v;
            }
        }
        __syncthreads();

        // online softmax: one thread per q row
        if (tid < BQ) {
            float* row = &Ps[tid * LDP];
            float rmax = -1e30f;
#pragma unroll 8
            for (int j = 0; j < BKV; j++) rmax = fmaxf(rmax, row[j]);
            float mo = m_sh[tid];
            float nm = fmaxf(mo, rmax);
            float al = __expf(mo - nm);
            float sum = 0.f;
#pragma unroll 8
            for (int j = 0; j < BKV; j++) {
                float p = __expf(row[j] - nm);
                row[j] = p;
                sum += p;
            }
            l_sh[tid]     = l_sh[tid] * al + sum;
            m_sh[tid]     = nm;
            alpha_sh[tid] = al;
        }
        __syncthreads();

        // O = O*alpha + P @ V
#pragma unroll
        for (int i = 0; i < 4; i++) {
            float al = alpha_sh[tr * 4 + i];
#pragma unroll
            for (int j = 0; j < 4; j++) acc[i][j] *= al;
        }
#pragma unroll 8
        for (int kk = 0; kk < BKV; kk++) {
            float p[4], vv[4];
#pragma unroll
            for (int i = 0; i < 4; i++) p[i]  = Ps[(tr * 4 + i) * LDP + kk];
#pragma unroll
            for (int j = 0; j < 4; j++) vv[j] = Vs[kk * LDP + (tc * 4 + j)];
#pragma unroll
            for (int i = 0; i < 4; i++)
#pragma unroll
                for (int j = 0; j < 4; j++) acc[i][j] += p[i] * vv[j];
        }
        __syncthreads();   // protect Ks/Vs/Ps before next iteration
    }

    // epilogue: normalize and write ctx in [B,S,H*hd] layout
#pragma unroll
    for (int i = 0; i < 4; i++) {
        float inv = 1.f / l_sh[tr * 4 + i];
#pragma unroll
        for (int j = 0; j < 4; j++) {
            g_ctx[base + (size_t)(q0 + tr * 4 + i) * DM + (tc * 4 + j)] =
                acc[i][j] * inv;
        }
    }
}

// ---------------------------------------------------------------------------
extern "C" void kernel_launch(void* const* d_in, const int* in_sizes, int n_in,
                              void* d_out, int out_size)
{
    const float* x  = (const float*)d_in[0];
    const float* Wq = (const float*)d_in[1];
    const float* Wk = (const float*)d_in[2];
    const float* Wv = (const float*)d_in[3];
    const float* Wo = (const float*)d_in[4];
    const float* bo = (const float*)d_in[5];
    float* out = (float*)d_out;

    // QKV projections: 3 GEMMs in one launch (z selects weight/output)
    dim3 gq(DM / 128, MROWS / 128, 3);
    qkv_kernel<<<gq, 256>>>(x, Wq, Wk, Wv);

    // Flash attention
    const int smem = 4 * BQ * LDP * sizeof(float);   // 66560 B
    cudaFuncSetAttribute(attn_kernel,
                         cudaFuncAttributeMaxDynamicSharedMemorySize, smem);
    attn_kernel<<<dim3(SS / BQ, NH, BB), 256, smem>>>();

    // Output projection + bias
    proj_kernel<<<dim3(DM / 128, MROWS / 128, 1), 256>>>(Wo, bo, out);
}

// round 3
// speedup vs baseline: 2.0514x; 2.0514x over previous
#include <cuda_runtime.h>
#include <cstddef>

// Problem constants
#define BB 2
#define SS 2048
#define DM 1024
#define NH 16
#define HD 64
#define MROWS (BB*SS)          // 4096

// Scratch (device globals — no runtime allocation allowed)
__device__ float g_q[MROWS * DM];
__device__ float g_k[MROWS * DM];
__device__ float g_v[MROWS * DM];
__device__ float g_ctx[MROWS * DM];

// ---------------------------------------------------------------------------
// tf32 helpers
// ---------------------------------------------------------------------------
__device__ __forceinline__ float tf32r(float x)
{
    asm("cvt.rna.tf32.f32 %0, %0;" : "+f"(x));
    return x;
}
__device__ __forceinline__ unsigned f2u(float x) { return __float_as_uint(x); }

// C[m16,n8] += A[m16,k8] * B[k8,n8], tf32 inputs, f32 accum
__device__ __forceinline__ void mma8(float* c, const unsigned* a, const unsigned* b)
{
    asm volatile(
        "mma.sync.aligned.m16n8k8.row.col.f32.tf32.tf32.f32 "
        "{%0,%1,%2,%3}, {%4,%5,%6,%7}, {%8,%9}, {%0,%1,%2,%3};\n"
        : "+f"(c[0]), "+f"(c[1]), "+f"(c[2]), "+f"(c[3])
        : "r"(a[0]), "r"(a[1]), "r"(a[2]), "r"(a[3]), "r"(b[0]), "r"(b[1]));
}

// ---------------------------------------------------------------------------
// tf32 MMA GEMM: C[M,1024] = A[M,1024] @ W[1024,1024] (+bias)
// 128x128 CTA tile, BK=16, 256 threads = 8 warps (2M x 4N), warp tile 64x32.
// Smem strides = 20 (== 4 mod 32) -> conflict-free fragment loads.
// ---------------------------------------------------------------------------
#define GBK 16
#define ASTR 20

__device__ __forceinline__ void gemm_mma(const float* __restrict__ A,
                                         const float* __restrict__ W,
                                         float* __restrict__ C,
                                         const float* __restrict__ bias)
{
    __shared__ float As[128 * ASTR];   // [m][k]
    __shared__ float Bs[128 * ASTR];   // [n][k] (transposed at load)

    const int tid  = threadIdx.x;
    const int wid  = tid >> 5;
    const int lane = tid & 31;
    const int g    = lane >> 2;        // 0..7
    const int t    = lane & 3;         // 0..3
    const int wm   = (wid >> 2) * 64;  // 0 / 64
    const int wn   = (wid & 3) * 32;   // 0 / 32 / 64 / 96
    const int m0   = blockIdx.y * 128;
    const int n0   = blockIdx.x * 128;

    float acc[4][4][4];
#pragma unroll
    for (int mt = 0; mt < 4; mt++)
#pragma unroll
        for (int nt = 0; nt < 4; nt++)
#pragma unroll
            for (int c = 0; c < 4; c++) acc[mt][nt][c] = 0.f;

    for (int k0 = 0; k0 < DM; k0 += GBK) {
        // A tile: 128 rows x 16 k (512 float4)
#pragma unroll
        for (int i = 0; i < 2; i++) {
            int f   = tid + i * 256;
            int row = f >> 2;
            int c4  = (f & 3) << 2;
            float4 v = *(const float4*)&A[(size_t)(m0 + row) * DM + k0 + c4];
            As[row * ASTR + c4 + 0] = tf32r(v.x);
            As[row * ASTR + c4 + 1] = tf32r(v.y);
            As[row * ASTR + c4 + 2] = tf32r(v.z);
            As[row * ASTR + c4 + 3] = tf32r(v.w);
        }
        // B tile: 16 k x 128 n, stored transposed Bs[n][k]
#pragma unroll
        for (int i = 0; i < 2; i++) {
            int f  = tid + i * 256;
            int r  = f >> 5;
            int c4 = (f & 31) << 2;
            float4 v = *(const float4*)&W[(size_t)(k0 + r) * DM + n0 + c4];
            Bs[(c4 + 0) * ASTR + r] = tf32r(v.x);
            Bs[(c4 + 1) * ASTR + r] = tf32r(v.y);
            Bs[(c4 + 2) * ASTR + r] = tf32r(v.z);
            Bs[(c4 + 3) * ASTR + r] = tf32r(v.w);
        }
        __syncthreads();

#pragma unroll
        for (int ks = 0; ks < 2; ks++) {
            const int ko = ks * 8;
            unsigned a[4][4], b[4][2];
#pragma unroll
            for (int mt = 0; mt < 4; mt++) {
                int r = wm + mt * 16 + g;
                a[mt][0] = f2u(As[r * ASTR + ko + t]);
                a[mt][1] = f2u(As[(r + 8) * ASTR + ko + t]);
                a[mt][2] = f2u(As[r * ASTR + ko + t + 4]);
                a[mt][3] = f2u(As[(r + 8) * ASTR + ko + t + 4]);
            }
#pragma unroll
            for (int nt = 0; nt < 4; nt++) {
                int n = wn + nt * 8 + g;
                b[nt][0] = f2u(Bs[n * ASTR + ko + t]);
                b[nt][1] = f2u(Bs[n * ASTR + ko + t + 4]);
            }
#pragma unroll
            for (int mt = 0; mt < 4; mt++)
#pragma unroll
                for (int nt = 0; nt < 4; nt++)
                    mma8(acc[mt][nt], a[mt], b[nt]);
        }
        __syncthreads();
    }

    // epilogue
#pragma unroll
    for (int mt = 0; mt < 4; mt++) {
        int r0 = m0 + wm + mt * 16 + g;
#pragma unroll
        for (int nt = 0; nt < 4; nt++) {
            int c0 = n0 + wn + nt * 8 + 2 * t;
            float bx = bias ? bias[c0] : 0.f;
            float by = bias ? bias[c0 + 1] : 0.f;
            *(float2*)&C[(size_t)r0 * DM + c0] =
                make_float2(acc[mt][nt][0] + bx, acc[mt][nt][1] + by);
            *(float2*)&C[(size_t)(r0 + 8) * DM + c0] =
                make_float2(acc[mt][nt][2] + bx, acc[mt][nt][3] + by);
        }
    }
}

__global__ void qkv_kernel(const float* __restrict__ X,
                           const float* __restrict__ Wq,
                           const float* __restrict__ Wk,
                           const float* __restrict__ Wv)
{
    const float* W;
    float* Out;
    if (blockIdx.z == 0)      { W = Wq; Out = g_q; }
    else if (blockIdx.z == 1) { W = Wk; Out = g_k; }
    else                      { W = Wv; Out = g_v; }
    gemm_mma(X, W, Out, nullptr);
}

__global__ void proj_kernel(const float* __restrict__ Wo,
                            const float* __restrict__ bo,
                            float* __restrict__ out)
{
    gemm_mma(g_ctx, Wo, out, bo);
}

// ---------------------------------------------------------------------------
// Flash attention with tf32 MMA. Block = (q-tile 64, head, batch), 128 thr
// = 4 warps; warp owns 16 q rows. KV tiles of 64. Online softmax in regs.
// Smem stride 68 (== 4 mod 32) -> conflict-free fragment loads.
// ---------------------------------------------------------------------------
#define ASTRD 68

__global__ void attn_kernel()
{
    extern __shared__ float sm[];
    float* Qs = sm;                    // [64][68]  Q[q][d]
    float* Ks = Qs + 64 * ASTRD;       // [64][68]  K[kv][d]
    float* Vs = Ks + 64 * ASTRD;       // [64][68]  V^T[d][kv]
    float* Ps = Vs + 64 * ASTRD;       // [64][68]  P[q][kv]

    const int qt   = blockIdx.x;
    const int h    = blockIdx.y;
    const int b    = blockIdx.z;
    const int q0   = qt * 64;
    const int tid  = threadIdx.x;
    const int wid  = tid >> 5;
    const int lane = tid & 31;
    const int g    = lane >> 2;
    const int t    = lane & 3;
    const size_t base = (size_t)b * SS * DM + (size_t)h * HD;

    // Load Q tile (tf32-rounded)
#pragma unroll
    for (int i = 0; i < 8; i++) {
        int f  = tid + i * 128;        // 0..1023 float4 slots
        int r  = f >> 4;
        int c4 = (f & 15) << 2;
        float4 v = *(const float4*)&g_q[base + (size_t)(q0 + r) * DM + c4];
        Qs[r * ASTRD + c4 + 0] = tf32r(v.x);
        Qs[r * ASTRD + c4 + 1] = tf32r(v.y);
        Qs[r * ASTRD + c4 + 2] = tf32r(v.z);
        Qs[r * ASTRD + c4 + 3] = tf32r(v.w);
    }

    float m[2] = {-1e30f, -1e30f};
    float l[2] = {0.f, 0.f};
    float o[8][4];
#pragma unroll
    for (int dt = 0; dt < 8; dt++)
#pragma unroll
        for (int c = 0; c < 4; c++) o[dt][c] = 0.f;

    const int qrow = wid * 16 + g;     // warp-local q row (lane's row0)

    for (int kt = 0; kt <= qt; kt++) {
        const int k0 = kt * 64;
        // Load K (as [kv][d]) and V (transposed, [d][kv])
#pragma unroll
        for (int i = 0; i < 8; i++) {
            int f  = tid + i * 128;
            int r  = f >> 4;
            int c4 = (f & 15) << 2;
            size_t gi = base + (size_t)(k0 + r) * DM + c4;
            float4 kv = *(const float4*)&g_k[gi];
            Ks[r * ASTRD + c4 + 0] = tf32r(kv.x);
            Ks[r * ASTRD + c4 + 1] = tf32r(kv.y);
            Ks[r * ASTRD + c4 + 2] = tf32r(kv.z);
            Ks[r * ASTRD + c4 + 3] = tf32r(kv.w);
            float4 vv = *(const float4*)&g_v[gi];
            Vs[(c4 + 0) * ASTRD + r] = tf32r(vv.x);
            Vs[(c4 + 1) * ASTRD + r] = tf32r(vv.y);
            Vs[(c4 + 2) * ASTRD + r] = tf32r(vv.z);
            Vs[(c4 + 3) * ASTRD + r] = tf32r(vv.w);
        }
        __syncthreads();

        // S = Q @ K^T (m16 x n64 per warp)
        float s[8][4];
#pragma unroll
        for (int nt = 0; nt < 8; nt++)
#pragma unroll
            for (int c = 0; c < 4; c++) s[nt][c] = 0.f;

#pragma unroll
        for (int kk = 0; kk < 8; kk++) {
            const int ko = kk * 8;
            unsigned a[4];
            a[0] = f2u(Qs[qrow * ASTRD + ko + t]);
            a[1] = f2u(Qs[(qrow + 8) * ASTRD + ko + t]);
            a[2] = f2u(Qs[qrow * ASTRD + ko + t + 4]);
            a[3] = f2u(Qs[(qrow + 8) * ASTRD + ko + t + 4]);
#pragma unroll
            for (int nt = 0; nt < 8; nt++) {
                unsigned bf[2];
                bf[0] = f2u(Ks[(nt * 8 + g) * ASTRD + ko + t]);
                bf[1] = f2u(Ks[(nt * 8 + g) * ASTRD + ko + t + 4]);
                mma8(s[nt], a, bf);
            }
        }

        // scale + causal mask
        const bool diag = (kt == qt);
        const int qr0 = q0 + qrow, qr1 = qr0 + 8;
#pragma unroll
        for (int nt = 0; nt < 8; nt++) {
            int kc0 = k0 + nt * 8 + 2 * t;
            int kc1 = kc0 + 1;
            s[nt][0] *= 0.125f;
            s[nt][1] *= 0.125f;
            s[nt][2] *= 0.125f;
            s[nt][3] *= 0.125f;
            if (diag) {
                if (kc0 > qr0) s[nt][0] = -1e30f;
                if (kc1 > qr0) s[nt][1] = -1e30f;
                if (kc0 > qr1) s[nt][2] = -1e30f;
                if (kc1 > qr1) s[nt][3] = -1e30f;
            }
        }

        // online softmax (rows qrow and qrow+8; cols spread over quad t)
        float rmax0 = -1e30f, rmax1 = -1e30f;
#pragma unroll
        for (int nt = 0; nt < 8; nt++) {
            rmax0 = fmaxf(rmax0, fmaxf(s[nt][0], s[nt][1]));
            rmax1 = fmaxf(rmax1, fmaxf(s[nt][2], s[nt][3]));
        }
        rmax0 = fmaxf(rmax0, __shfl_xor_sync(0xffffffffu, rmax0, 1));
        rmax0 = fmaxf(rmax0, __shfl_xor_sync(0xffffffffu, rmax0, 2));
        rmax1 = fmaxf(rmax1, __shfl_xor_sync(0xffffffffu, rmax1, 1));
        rmax1 = fmaxf(rmax1, __shfl_xor_sync(0xffffffffu, rmax1, 2));

        float mn0 = fmaxf(m[0], rmax0);
        float mn1 = fmaxf(m[1], rmax1);
        float al0 = __expf(m[0] - mn0);
        float al1 = __expf(m[1] - mn1);
        float sum0 = 0.f, sum1 = 0.f;
#pragma unroll
        for (int nt = 0; nt < 8; nt++) {
            s[nt][0] = __expf(s[nt][0] - mn0);
            s[nt][1] = __expf(s[nt][1] - mn0);
            s[nt][2] = __expf(s[nt][2] - mn1);
            s[nt][3] = __expf(s[nt][3] - mn1);
            sum0 += s[nt][0] + s[nt][1];
            sum1 += s[nt][2] + s[nt][3];
        }
        sum0 += __shfl_xor_sync(0xffffffffu, sum0, 1);
        sum0 += __shfl_xor_sync(0xffffffffu, sum0, 2);
        sum1 += __shfl_xor_sync(0xffffffffu, sum1, 1);
        sum1 += __shfl_xor_sync(0xffffffffu, sum1, 2);

        l[0] = l[0] * al0 + sum0;
        l[1] = l[1] * al1 + sum1;
        m[0] = mn0;
        m[1] = mn1;
#pragma unroll
        for (int dt = 0; dt < 8; dt++) {
            o[dt][0] *= al0;
            o[dt][1] *= al0;
            o[dt][2] *= al1;
            o[dt][3] *= al1;
        }

        // store P (tf32) to shared; warp reads back only its own rows
#pragma unroll
        for (int nt = 0; nt < 8; nt++) {
            int c0 = nt * 8 + 2 * t;
            *(float2*)&Ps[qrow * ASTRD + c0] =
                make_float2(tf32r(s[nt][0]), tf32r(s[nt][1]));
            *(float2*)&Ps[(qrow + 8) * ASTRD + c0] =
                make_float2(tf32r(s[nt][2]), tf32r(s[nt][3]));
        }
        __syncwarp();

        // O += P @ V
#pragma unroll
        for (int kk = 0; kk < 8; kk++) {
            const int ko = kk * 8;
            unsigned a[4];
            a[0] = f2u(Ps[qrow * ASTRD + ko + t]);
            a[1] = f2u(Ps[(qrow + 8) * ASTRD + ko + t]);
            a[2] = f2u(Ps[qrow * ASTRD + ko + t + 4]);
            a[3] = f2u(Ps[(qrow + 8) * ASTRD + ko + t + 4]);
#pragma unroll
            for (int dt = 0; dt < 8; dt++) {
                unsigned bf[2];
                bf[0] = f2u(Vs[(dt * 8 + g) * ASTRD + ko + t]);
                bf[1] = f2u(Vs[(dt * 8 + g) * ASTRD + ko + t + 4]);
                mma8(o[dt], a, bf);
            }
        }
        __syncthreads();   // Ks/Vs reused next iteration
    }

    // epilogue: normalize, write ctx [B,S,H*hd]
    const float inv0 = 1.f / l[0];
    const float inv1 = 1.f / l[1];
#pragma unroll
    for (int dt = 0; dt < 8; dt++) {
        int c = dt * 8 + 2 * t;
        size_t i0 = base + (size_t)(q0 + qrow) * DM + c;
        size_t i1 = base + (size_t)(q0 + qrow + 8) * DM + c;
        *(float2*)&g_ctx[i0] = make_float2(o[dt][0] * inv0, o[dt][1] * inv0);
        *(float2*)&g_ctx[i1] = make_float2(o[dt][2] * inv1, o[dt][3] * inv1);
    }
}

// ---------------------------------------------------------------------------
extern "C" void kernel_launch(void* const* d_in, const int* in_sizes, int n_in,
                              void* d_out, int out_size)
{
    const float* x  = (const float*)d_in[0];
    const float* Wq = (const float*)d_in[1];
    const float* Wk = (const float*)d_in[2];
    const float* Wv = (const float*)d_in[3];
    const float* Wo = (const float*)d_in[4];
    const float* bo = (const float*)d_in[5];
    float* out = (float*)d_out;

    dim3 gq(DM / 128, MROWS / 128, 3);
    qkv_kernel<<<gq, 256>>>(x, Wq, Wk, Wv);

    const int smem = 4 * 64 * ASTRD * sizeof(float);   // 69632 B
    cudaFuncSetAttribute(attn_kernel,
                         cudaFuncAttributeMaxDynamicSharedMemorySize, smem);
    attn_kernel<<<dim3(SS / 64, NH, BB), 128, smem>>>();

    proj_kernel<<<dim3(DM / 128, MROWS / 128, 1), 256>>>(Wo, bo, out);
}

// round 4
// speedup vs baseline: 2.1950x; 1.0700x over previous
#include <cuda_runtime.h>
#include <cstddef>

// Problem constants
#define BB 2
#define SS 2048
#define DM 1024
#define NH 16
#define HD 64
#define MROWS (BB*SS)          // 4096

// Scratch (device globals — no runtime allocation allowed)
__device__ float g_q[MROWS * DM];
__device__ float g_k[MROWS * DM];
__device__ float g_v[MROWS * DM];
__device__ float g_ctx[MROWS * DM];

// ---------------------------------------------------------------------------
// tf32 helpers
// ---------------------------------------------------------------------------
__device__ __forceinline__ float tf32r(float x)
{
    asm("cvt.rna.tf32.f32 %0, %0;" : "+f"(x));
    return x;
}
__device__ __forceinline__ unsigned f2u(float x) { return __float_as_uint(x); }

// C[m16,n8] += A[m16,k8] * B[k8,n8], tf32 inputs, f32 accum
__device__ __forceinline__ void mma8(float* c, const unsigned* a, const unsigned* b)
{
    asm volatile(
        "mma.sync.aligned.m16n8k8.row.col.f32.tf32.tf32.f32 "
        "{%0,%1,%2,%3}, {%4,%5,%6,%7}, {%8,%9}, {%0,%1,%2,%3};\n"
        : "+f"(c[0]), "+f"(c[1]), "+f"(c[2]), "+f"(c[3])
        : "r"(a[0]), "r"(a[1]), "r"(a[2]), "r"(a[3]), "r"(b[0]), "r"(b[1]));
}

// ---------------------------------------------------------------------------
// tf32 MMA GEMM: C[M,1024] = A[M,1024] @ W[1024,1024] (+bias)
// 128x128 CTA tile, BK=16, 256 threads = 8 warps (2M x 4N), warp tile 64x32.
// Double-buffered smem + register prefetch of the next tile; ONE sync/iter.
// Smem strides = 20 (== 4 mod 32) -> conflict-free fragment loads.
// ---------------------------------------------------------------------------
#define GBK 16
#define ASTR 20

__device__ __forceinline__ void gemm_mma(const float* __restrict__ A,
                                         const float* __restrict__ W,
                                         float* __restrict__ C,
                                         const float* __restrict__ bias)
{
    __shared__ float As[2][128 * ASTR];   // [m][k]
    __shared__ float Bs[2][128 * ASTR];   // [n][k] (transposed at load)

    const int tid  = threadIdx.x;
    const int wid  = tid >> 5;
    const int lane = tid & 31;
    const int g    = lane >> 2;        // 0..7
    const int t    = lane & 3;         // 0..3
    const int wm   = (wid >> 2) * 64;  // 0 / 64
    const int wn   = (wid & 3) * 32;   // 0 / 32 / 64 / 96
    const int m0   = blockIdx.y * 128;
    const int n0   = blockIdx.x * 128;

    // loader coordinates (2 float4 per tensor per thread)
    const int ar0 = tid >> 2;                 // A rows for i=0,1: ar0, ar0+64
    const int ac4 = (tid & 3) << 2;           // A k-offset
    const int br  = tid >> 5;                 // B k rows: br, br+8
    const int bc4 = (tid & 31) << 2;          // B n-offset

    float acc[4][4][4];
#pragma unroll
    for (int mt = 0; mt < 4; mt++)
#pragma unroll
        for (int nt = 0; nt < 4; nt++)
#pragma unroll
            for (int c = 0; c < 4; c++) acc[mt][nt][c] = 0.f;

    float4 pa[2], pb[2];

    // prologue: load + stage tile 0
#pragma unroll
    for (int i = 0; i < 2; i++) {
        pa[i] = *(const float4*)&A[(size_t)(m0 + ar0 + i * 64) * DM + ac4];
        pb[i] = *(const float4*)&W[(size_t)(br + i * 8) * DM + n0 + bc4];
    }
#pragma unroll
    for (int i = 0; i < 2; i++) {
        int row = ar0 + i * 64;
        As[0][row * ASTR + ac4 + 0] = tf32r(pa[i].x);
        As[0][row * ASTR + ac4 + 1] = tf32r(pa[i].y);
        As[0][row * ASTR + ac4 + 2] = tf32r(pa[i].z);
        As[0][row * ASTR + ac4 + 3] = tf32r(pa[i].w);
        int r = br + i * 8;
        Bs[0][(bc4 + 0) * ASTR + r] = tf32r(pb[i].x);
        Bs[0][(bc4 + 1) * ASTR + r] = tf32r(pb[i].y);
        Bs[0][(bc4 + 2) * ASTR + r] = tf32r(pb[i].z);
        Bs[0][(bc4 + 3) * ASTR + r] = tf32r(pb[i].w);
    }
    __syncthreads();

    int buf = 0;
    for (int k0 = 0; k0 < DM; k0 += GBK) {
        const bool more = (k0 + GBK) < DM;
        // prefetch next tile (overlaps with the MMAs below)
        if (more) {
            const int kn = k0 + GBK;
#pragma unroll
            for (int i = 0; i < 2; i++) {
                pa[i] = *(const float4*)&A[(size_t)(m0 + ar0 + i * 64) * DM + kn + ac4];
                pb[i] = *(const float4*)&W[(size_t)(kn + br + i * 8) * DM + n0 + bc4];
            }
        }

        const float* __restrict__ as = As[buf];
        const float* __restrict__ bs = Bs[buf];
#pragma unroll
        for (int ks = 0; ks < 2; ks++) {
            const int ko = ks * 8;
            unsigned a[4][4], b[4][2];
#pragma unroll
            for (int mt = 0; mt < 4; mt++) {
                int r = wm + mt * 16 + g;
                a[mt][0] = f2u(as[r * ASTR + ko + t]);
                a[mt][1] = f2u(as[(r + 8) * ASTR + ko + t]);
                a[mt][2] = f2u(as[r * ASTR + ko + t + 4]);
                a[mt][3] = f2u(as[(r + 8) * ASTR + ko + t + 4]);
            }
#pragma unroll
            for (int nt = 0; nt < 4; nt++) {
                int n = wn + nt * 8 + g;
                b[nt][0] = f2u(bs[n * ASTR + ko + t]);
                b[nt][1] = f2u(bs[n * ASTR + ko + t + 4]);
            }
#pragma unroll
            for (int mt = 0; mt < 4; mt++)
#pragma unroll
                for (int nt = 0; nt < 4; nt++)
                    mma8(acc[mt][nt], a[mt], b[nt]);
        }

        // stage next tile into the other buffer
        if (more) {
            float* an = As[buf ^ 1];
            float* bn = Bs[buf ^ 1];
#pragma unroll
            for (int i = 0; i < 2; i++) {
                int row = ar0 + i * 64;
                an[row * ASTR + ac4 + 0] = tf32r(pa[i].x);
                an[row * ASTR + ac4 + 1] = tf32r(pa[i].y);
                an[row * ASTR + ac4 + 2] = tf32r(pa[i].z);
                an[row * ASTR + ac4 + 3] = tf32r(pa[i].w);
                int r = br + i * 8;
                bn[(bc4 + 0) * ASTR + r] = tf32r(pb[i].x);
                bn[(bc4 + 1) * ASTR + r] = tf32r(pb[i].y);
                bn[(bc4 + 2) * ASTR + r] = tf32r(pb[i].z);
                bn[(bc4 + 3) * ASTR + r] = tf32r(pb[i].w);
            }
        }
        __syncthreads();
        buf ^= 1;
    }

    // epilogue
#pragma unroll
    for (int mt = 0; mt < 4; mt++) {
        int r0 = m0 + wm + mt * 16 + g;
#pragma unroll
        for (int nt = 0; nt < 4; nt++) {
            int c0 = n0 + wn + nt * 8 + 2 * t;
            float bx = bias ? bias[c0] : 0.f;
            float by = bias ? bias[c0 + 1] : 0.f;
            *(float2*)&C[(size_t)r0 * DM + c0] =
                make_float2(acc[mt][nt][0] + bx, acc[mt][nt][1] + by);
            *(float2*)&C[(size_t)(r0 + 8) * DM + c0] =
                make_float2(acc[mt][nt][2] + bx, acc[mt][nt][3] + by);
        }
    }
}

__global__ void __launch_bounds__(256, 2)
qkv_kernel(const float* __restrict__ X,
           const float* __restrict__ Wq,
           const float* __restrict__ Wk,
           const float* __restrict__ Wv)
{
    const float* W;
    float* Out;
    if (blockIdx.z == 0)      { W = Wq; Out = g_q; }
    else if (blockIdx.z == 1) { W = Wk; Out = g_k; }
    else                      { W = Wv; Out = g_v; }
    gemm_mma(X, W, Out, nullptr);
}

__global__ void __launch_bounds__(256, 2)
proj_kernel(const float* __restrict__ Wo,
            const float* __restrict__ bo,
            float* __restrict__ out)
{
    gemm_mma(g_ctx, Wo, out, bo);
}

// ---------------------------------------------------------------------------
// Flash attention with tf32 MMA. Block = (q-tile 64, head, batch), 128 thr
// = 4 warps; warp owns 16 q rows. KV tiles of 64. Online softmax in regs.
// Smem stride 68 (== 4 mod 32) -> conflict-free fragment loads.
// ---------------------------------------------------------------------------
#define ASTRD 68

__global__ void attn_kernel()
{
    extern __shared__ float sm[];
    float* Qs = sm;                    // [64][68]  Q[q][d]
    float* Ks = Qs + 64 * ASTRD;       // [64][68]  K[kv][d]
    float* Vs = Ks + 64 * ASTRD;       // [64][68]  V^T[d][kv]
    float* Ps = Vs + 64 * ASTRD;       // [64][68]  P[q][kv]

    const int qt   = blockIdx.x;
    const int h    = blockIdx.y;
    const int b    = blockIdx.z;
    const int q0   = qt * 64;
    const int tid  = threadIdx.x;
    const int wid  = tid >> 5;
    const int lane = tid & 31;
    const int g    = lane >> 2;
    const int t    = lane & 3;
    const size_t base = (size_t)b * SS * DM + (size_t)h * HD;

    // Load Q tile (tf32-rounded)
#pragma unroll
    for (int i = 0; i < 8; i++) {
        int f  = tid + i * 128;        // 0..1023 float4 slots
        int r  = f >> 4;
        int c4 = (f & 15) << 2;
        float4 v = *(const float4*)&g_q[base + (size_t)(q0 + r) * DM + c4];
        Qs[r * ASTRD + c4 + 0] = tf32r(v.x);
        Qs[r * ASTRD + c4 + 1] = tf32r(v.y);
        Qs[r * ASTRD + c4 + 2] = tf32r(v.z);
        Qs[r * ASTRD + c4 + 3] = tf32r(v.w);
    }

    float m[2] = {-1e30f, -1e30f};
    float l[2] = {0.f, 0.f};
    float o[8][4];
#pragma unroll
    for (int dt = 0; dt < 8; dt++)
#pragma unroll
        for (int c = 0; c < 4; c++) o[dt][c] = 0.f;

    const int qrow = wid * 16 + g;     // warp-local q row (lane's row0)

    for (int kt = 0; kt <= qt; kt++) {
        const int k0 = kt * 64;
        // Load K (as [kv][d]) and V (transposed, [d][kv])
#pragma unroll
        for (int i = 0; i < 8; i++) {
            int f  = tid + i * 128;
            int r  = f >> 4;
            int c4 = (f & 15) << 2;
            size_t gi = base + (size_t)(k0 + r) * DM + c4;
            float4 kv = *(const float4*)&g_k[gi];
            Ks[r * ASTRD + c4 + 0] = tf32r(kv.x);
            Ks[r * ASTRD + c4 + 1] = tf32r(kv.y);
            Ks[r * ASTRD + c4 + 2] = tf32r(kv.z);
            Ks[r * ASTRD + c4 + 3] = tf32r(kv.w);
            float4 vv = *(const float4*)&g_v[gi];
            Vs[(c4 + 0) * ASTRD + r] = tf32r(vv.x);
            Vs[(c4 + 1) * ASTRD + r] = tf32r(vv.y);
            Vs[(c4 + 2) * ASTRD + r] = tf32r(vv.z);
            Vs[(c4 + 3) * ASTRD + r] = tf32r(vv.w);
        }
        __syncthreads();

        // S = Q @ K^T (m16 x n64 per warp)
        float s[8][4];
#pragma unroll
        for (int nt = 0; nt < 8; nt++)
#pragma unroll
            for (int c = 0; c < 4; c++) s[nt][c] = 0.f;

#pragma unroll
        for (int kk = 0; kk < 8; kk++) {
            const int ko = kk * 8;
            unsigned a[4];
            a[0] = f2u(Qs[qrow * ASTRD + ko + t]);
            a[1] = f2u(Qs[(qrow + 8) * ASTRD + ko + t]);
            a[2] = f2u(Qs[qrow * ASTRD + ko + t + 4]);
            a[3] = f2u(Qs[(qrow + 8) * ASTRD + ko + t + 4]);
#pragma unroll
            for (int nt = 0; nt < 8; nt++) {
                unsigned bf[2];
                bf[0] = f2u(Ks[(nt * 8 + g) * ASTRD + ko + t]);
                bf[1] = f2u(Ks[(nt * 8 + g) * ASTRD + ko + t + 4]);
                mma8(s[nt], a, bf);
            }
        }

        // scale + causal mask
        const bool diag = (kt == qt);
        const int qr0 = q0 + qrow, qr1 = qr0 + 8;
#pragma unroll
        for (int nt = 0; nt < 8; nt++) {
            int kc0 = k0 + nt * 8 + 2 * t;
            int kc1 = kc0 + 1;
            s[nt][0] *= 0.125f;
            s[nt][1] *= 0.125f;
            s[nt][2] *= 0.125f;
            s[nt][3] *= 0.125f;
            if (diag) {
                if (kc0 > qr0) s[nt][0] = -1e30f;
                if (kc1 > qr0) s[nt][1] = -1e30f;
                if (kc0 > qr1) s[nt][2] = -1e30f;
                if (kc1 > qr1) s[nt][3] = -1e30f;
            }
        }

        // online softmax (rows qrow and qrow+8; cols spread over quad t)
        float rmax0 = -1e30f, rmax1 = -1e30f;
#pragma unroll
        for (int nt = 0; nt < 8; nt++) {
            rmax0 = fmaxf(rmax0, fmaxf(s[nt][0], s[nt][1]));
            rmax1 = fmaxf(rmax1, fmaxf(s[nt][2], s[nt][3]));
        }
        rmax0 = fmaxf(rmax0, __shfl_xor_sync(0xffffffffu, rmax0, 1));
        rmax0 = fmaxf(rmax0, __shfl_xor_sync(0xffffffffu, rmax0, 2));
        rmax1 = fmaxf(rmax1, __shfl_xor_sync(0xffffffffu, rmax1, 1));
        rmax1 = fmaxf(rmax1, __shfl_xor_sync(0xffffffffu, rmax1, 2));

        float mn0 = fmaxf(m[0], rmax0);
        float mn1 = fmaxf(m[1], rmax1);
        float al0 = __expf(m[0] - mn0);
        float al1 = __expf(m[1] - mn1);
        float sum0 = 0.f, sum1 = 0.f;
#pragma unroll
        for (int nt = 0; nt < 8; nt++) {
            s[nt][0] = __expf(s[nt][0] - mn0);
            s[nt][1] = __expf(s[nt][1] - mn0);
            s[nt][2] = __expf(s[nt][2] - mn1);
            s[nt][3] = __expf(s[nt][3] - mn1);
            sum0 += s[nt][0] + s[nt][1];
            sum1 += s[nt][2] + s[nt][3];
        }
        sum0 += __shfl_xor_sync(0xffffffffu, sum0, 1);
        sum0 += __shfl_xor_sync(0xffffffffu, sum0, 2);
        sum1 += __shfl_xor_sync(0xffffffffu, sum1, 1);
        sum1 += __shfl_xor_sync(0xffffffffu, sum1, 2);

        l[0] = l[0] * al0 + sum0;
        l[1] = l[1] * al1 + sum1;
        m[0] = mn0;
        m[1] = mn1;
#pragma unroll
        for (int dt = 0; dt < 8; dt++) {
            o[dt][0] *= al0;
            o[dt][1] *= al0;
            o[dt][2] *= al1;
            o[dt][3] *= al1;
        }

        // store P (tf32) to shared; warp reads back only its own rows
#pragma unroll
        for (int nt = 0; nt < 8; nt++) {
            int c0 = nt * 8 + 2 * t;
            *(float2*)&Ps[qrow * ASTRD + c0] =
                make_float2(tf32r(s[nt][0]), tf32r(s[nt][1]));
            *(float2*)&Ps[(qrow + 8) * ASTRD + c0] =
                make_float2(tf32r(s[nt][2]), tf32r(s[nt][3]));
        }
        __syncwarp();

        // O += P @ V
#pragma unroll
        for (int kk = 0; kk < 8; kk++) {
            const int ko = kk * 8;
            unsigned a[4];
            a[0] = f2u(Ps[qrow * ASTRD + ko + t]);
            a[1] = f2u(Ps[(qrow + 8) * ASTRD + ko + t]);
            a[2] = f2u(Ps[qrow * ASTRD + ko + t + 4]);
            a[3] = f2u(Ps[(qrow + 8) * ASTRD + ko + t + 4]);
#pragma unroll
            for (int dt = 0; dt < 8; dt++) {
                unsigned bf[2];
                bf[0] = f2u(Vs[(dt * 8 + g) * ASTRD + ko + t]);
                bf[1] = f2u(Vs[(dt * 8 + g) * ASTRD + ko + t + 4]);
                mma8(o[dt], a, bf);
            }
        }
        __syncthreads();   // Ks/Vs reused next iteration
    }

    // epilogue: normalize, write ctx [B,S,H*hd]
    const float inv0 = 1.f / l[0];
    const float inv1 = 1.f / l[1];
#pragma unroll
    for (int dt = 0; dt < 8; dt++) {
        int c = dt * 8 + 2 * t;
        size_t i0 = base + (size_t)(q0 + qrow) * DM + c;
        size_t i1 = base + (size_t)(q0 + qrow + 8) * DM + c;
        *(float2*)&g_ctx[i0] = make_float2(o[dt][0] * inv0, o[dt][1] * inv0);
        *(float2*)&g_ctx[i1] = make_float2(o[dt][2] * inv1, o[dt][3] * inv1);
    }
}

// ---------------------------------------------------------------------------
extern "C" void kernel_launch(void* const* d_in, const int* in_sizes, int n_in,
                              void* d_out, int out_size)
{
    const float* x  = (const float*)d_in[0];
    const float* Wq = (const float*)d_in[1];
    const float* Wk = (const float*)d_in[2];
    const float* Wv = (const float*)d_in[3];
    const float* Wo = (const float*)d_in[4];
    const float* bo = (const float*)d_in[5];
    float* out = (float*)d_out;

    dim3 gq(DM / 128, MROWS / 128, 3);
    qkv_kernel<<<gq, 256>>>(x, Wq, Wk, Wv);

    const int smem = 4 * 64 * ASTRD * sizeof(float);   // 69632 B
    cudaFuncSetAttribute(attn_kernel,
                         cudaFuncAttributeMaxDynamicSharedMemorySize, smem);
    attn_kernel<<<dim3(SS / 64, NH, BB), 128, smem>>>();

    proj_kernel<<<dim3(DM / 128, MROWS / 128, 1), 256>>>(Wo, bo, out);
}

// round 6
// speedup vs baseline: 3.4824x; 1.5865x over previous
#include <cuda_runtime.h>
#include <cstddef>

// Problem constants
#define BB 2
#define SS 2048
#define DM 1024
#define NH 16
#define HD 64
#define MROWS (BB*SS)          // 4096

// Scratch (device globals — no runtime allocation allowed)
__device__ float g_q[MROWS * DM];
__device__ float g_k[MROWS * DM];
__device__ float g_v[MROWS * DM];
__device__ float g_ctx[MROWS * DM];

// ---------------------------------------------------------------------------
// tf32 helpers
// ---------------------------------------------------------------------------
__device__ __forceinline__ float tf32r(float x)
{
    asm("cvt.rna.tf32.f32 %0, %0;" : "+f"(x));
    return x;
}
__device__ __forceinline__ unsigned f2u(float x) { return __float_as_uint(x); }

// C[m16,n8] += A[m16,k8] * B[k8,n8], tf32 inputs, f32 accum
__device__ __forceinline__ void mma8(float* c, const unsigned* a, const unsigned* b)
{
    asm volatile(
        "mma.sync.aligned.m16n8k8.row.col.f32.tf32.tf32.f32 "
        "{%0,%1,%2,%3}, {%4,%5,%6,%7}, {%8,%9}, {%0,%1,%2,%3};\n"
        : "+f"(c[0]), "+f"(c[1]), "+f"(c[2]), "+f"(c[3])
        : "r"(a[0]), "r"(a[1]), "r"(a[2]), "r"(a[3]), "r"(b[0]), "r"(b[1]));
}

// ---------------------------------------------------------------------------
// tf32 MMA GEMM: C[M,1024] = A[M,1024] @ W[1024,1024] (+bias)
// 128x128 CTA tile, BK=16, 256 thr = 8 warps (2M x 4N), warp tile 64x32.
// As: [m][perm(k)] stride 24 -> float2 fragment loads, conflict-free.
// Bs: [k][n] natural, stride 152 -> float4 STS + scalar loads, conflict-free.
// Double-buffered smem + register prefetch, one syncthreads per iter.
// ---------------------------------------------------------------------------
#define GBK 16
#define ASTR 24
#define BSTR 152

__device__ __forceinline__ void gemm_mma(const float* __restrict__ A,
                                         const float* __restrict__ W,
                                         float* __restrict__ C,
                                         const float* __restrict__ bias)
{
    __shared__ float As[2][128 * ASTR];   // [m][perm k]
    __shared__ float Bs[2][GBK * BSTR];   // [k][n]

    const int tid  = threadIdx.x;
    const int wid  = tid >> 5;
    const int lane = tid & 31;
    const int g    = lane >> 2;        // 0..7
    const int t    = lane & 3;         // 0..3
    const int wm   = (wid >> 2) * 64;  // 0 / 64
    const int wn   = (wid & 3) * 32;   // 0 / 32 / 64 / 96
    const int m0   = blockIdx.y * 128;
    const int n0   = blockIdx.x * 128;

    // loader coordinates
    const int ar0 = tid >> 2;                 // A rows: ar0, ar0+64
    const int ac4 = (tid & 3) << 2;           // A logical k offset {0,4,8,12}
    const int apb = (ac4 & 8) | ((ac4 >> 2) & 1);  // permuted base col
    const int br  = tid >> 5;                 // B k rows: br, br+8
    const int bc4 = (tid & 31) << 2;          // B n offset

    float acc[4][4][4];
#pragma unroll
    for (int mt = 0; mt < 4; mt++)
#pragma unroll
        for (int nt = 0; nt < 4; nt++)
#pragma unroll
            for (int c = 0; c < 4; c++) acc[mt][nt][c] = 0.f;

    float4 pa[2], pb[2];

#pragma unroll
    for (int i = 0; i < 2; i++) {
        pa[i] = *(const float4*)&A[(size_t)(m0 + ar0 + i * 64) * DM + ac4];
        pb[i] = *(const float4*)&W[(size_t)(br + i * 8) * DM + n0 + bc4];
    }
#pragma unroll
    for (int i = 0; i < 2; i++) {
        int row = ar0 + i * 64;
        As[0][row * ASTR + apb + 0] = tf32r(pa[i].x);
        As[0][row * ASTR + apb + 2] = tf32r(pa[i].y);
        As[0][row * ASTR + apb + 4] = tf32r(pa[i].z);
        As[0][row * ASTR + apb + 6] = tf32r(pa[i].w);
        int r = br + i * 8;
        *(float4*)&Bs[0][r * BSTR + bc4] =
            make_float4(tf32r(pb[i].x), tf32r(pb[i].y),
                        tf32r(pb[i].z), tf32r(pb[i].w));
    }
    __syncthreads();

    int buf = 0;
    for (int k0 = 0; k0 < DM; k0 += GBK) {
        const bool more = (k0 + GBK) < DM;
        if (more) {
            const int kn = k0 + GBK;
#pragma unroll
            for (int i = 0; i < 2; i++) {
                pa[i] = *(const float4*)&A[(size_t)(m0 + ar0 + i * 64) * DM + kn + ac4];
                pb[i] = *(const float4*)&W[(size_t)(kn + br + i * 8) * DM + n0 + bc4];
            }
        }

        const float* __restrict__ as = As[buf];
        const float* __restrict__ bs = Bs[buf];
#pragma unroll
        for (int ks = 0; ks < 2; ks++) {
            const int ko = ks * 8;
            unsigned a[4][4], b[4][2];
#pragma unroll
            for (int mt = 0; mt < 4; mt++) {
                int r = wm + mt * 16 + g;
                float2 f0 = *(const float2*)&as[r * ASTR + ko + 2 * t];
                float2 f1 = *(const float2*)&as[(r + 8) * ASTR + ko + 2 * t];
                a[mt][0] = f2u(f0.x);
                a[mt][1] = f2u(f1.x);
                a[mt][2] = f2u(f0.y);
                a[mt][3] = f2u(f1.y);
            }
#pragma unroll
            for (int nt = 0; nt < 4; nt++) {
                int n = wn + nt * 8 + g;
                b[nt][0] = f2u(bs[(ko + t) * BSTR + n]);
                b[nt][1] = f2u(bs[(ko + t + 4) * BSTR + n]);
            }
#pragma unroll
            for (int mt = 0; mt < 4; mt++)
#pragma unroll
                for (int nt = 0; nt < 4; nt++)
                    mma8(acc[mt][nt], a[mt], b[nt]);
        }

        if (more) {
            float* an = As[buf ^ 1];
            float* bn = Bs[buf ^ 1];
#pragma unroll
            for (int i = 0; i < 2; i++) {
                int row = ar0 + i * 64;
                an[row * ASTR + apb + 0] = tf32r(pa[i].x);
                an[row * ASTR + apb + 2] = tf32r(pa[i].y);
                an[row * ASTR + apb + 4] = tf32r(pa[i].z);
                an[row * ASTR + apb + 6] = tf32r(pa[i].w);
                int r = br + i * 8;
                *(float4*)&bn[r * BSTR + bc4] =
                    make_float4(tf32r(pb[i].x), tf32r(pb[i].y),
                                tf32r(pb[i].z), tf32r(pb[i].w));
            }
        }
        __syncthreads();
        buf ^= 1;
    }

    // epilogue
#pragma unroll
    for (int mt = 0; mt < 4; mt++) {
        int r0 = m0 + wm + mt * 16 + g;
#pragma unroll
        for (int nt = 0; nt < 4; nt++) {
            int c0 = n0 + wn + nt * 8 + 2 * t;
            float bx = bias ? bias[c0] : 0.f;
            float by = bias ? bias[c0 + 1] : 0.f;
            *(float2*)&C[(size_t)r0 * DM + c0] =
                make_float2(acc[mt][nt][0] + bx, acc[mt][nt][1] + by);
            *(float2*)&C[(size_t)(r0 + 8) * DM + c0] =
                make_float2(acc[mt][nt][2] + bx, acc[mt][nt][3] + by);
        }
    }
}

__global__ void __launch_bounds__(256, 2)
qkv_kernel(const float* __restrict__ X,
           const float* __restrict__ Wq,
           const float* __restrict__ Wk,
           const float* __restrict__ Wv)
{
    const float* W;
    float* Out;
    if (blockIdx.z == 0)      { W = Wq; Out = g_q; }
    else if (blockIdx.z == 1) { W = Wk; Out = g_k; }
    else                      { W = Wv; Out = g_v; }
    gemm_mma(X, W, Out, nullptr);
}

__global__ void __launch_bounds__(256, 2)
proj_kernel(const float* __restrict__ Wo,
            const float* __restrict__ bo,
            float* __restrict__ out)
{
    gemm_mma(g_ctx, Wo, out, bo);
}

// ---------------------------------------------------------------------------
// Flash attention, tf32 MMA. Block = (64 q rows, head, batch), 128 thr.
// Qs/Ps: [row][perm(k)] stride 72 -> float2 A-frag loads.
// Ks:    [kv][d] stride 68, float4 STS, scalar B-frags (bank 4g+t).
// Vs:    [kv][d] stride 72, float4 STS, scalar B-frags (bank 8t+g).
// K/V register prefetch overlaps next tile's LDG with compute.
// ---------------------------------------------------------------------------
#define QSTR 72
#define KSTR 68

__global__ void __launch_bounds__(128, 2) attn_kernel()
{
    extern __shared__ float sm[];
    float* Qs = sm;                    // [64][72]
    float* Ks = Qs + 64 * QSTR;        // [64][68]
    float* Vs = Ks + 64 * KSTR;        // [64][72]
    float* Ps = Vs + 64 * QSTR;        // [64][72]

    const int qt   = blockIdx.x;
    const int h    = blockIdx.y;
    const int b    = blockIdx.z;
    const int q0   = qt * 64;
    const int tid  = threadIdx.x;
    const int wid  = tid >> 5;
    const int lane = tid & 31;
    const int g    = lane >> 2;
    const int t    = lane & 3;
    const size_t base = (size_t)b * SS * DM + (size_t)h * HD;

    // Load Q tile into permuted layout
#pragma unroll
    for (int i = 0; i < 8; i++) {
        int f  = tid + i * 128;
        int r  = f >> 4;
        int c4 = (f & 15) << 2;
        int pbq = (c4 & ~7) | ((c4 >> 2) & 1);
        float4 v = *(const float4*)&g_q[base + (size_t)(q0 + r) * DM + c4];
        Qs[r * QSTR + pbq + 0] = tf32r(v.x);
        Qs[r * QSTR + pbq + 2] = tf32r(v.y);
        Qs[r * QSTR + pbq + 4] = tf32r(v.z);
        Qs[r * QSTR + pbq + 6] = tf32r(v.w);
    }

    float m[2] = {-1e30f, -1e30f};
    float l[2] = {0.f, 0.f};
    float o[8][4];
#pragma unroll
    for (int dt = 0; dt < 8; dt++)
#pragma unroll
        for (int c = 0; c < 4; c++) o[dt][c] = 0.f;

    const int qrow = wid * 16 + g;
    // P write positions: logical kv (2t, 2t+1) -> perm (p0, p0+2)
    const int p0 = ((t & 1) << 2) | (t >> 1);

    // prefetch KV tile 0
    float4 kreg[8], vreg[8];
#pragma unroll
    for (int i = 0; i < 8; i++) {
        int f  = tid + i * 128;
        int r  = f >> 4;
        int c4 = (f & 15) << 2;
        size_t gi = base + (size_t)(r) * DM + c4;
        kreg[i] = *(const float4*)&g_k[gi];
        vreg[i] = *(const float4*)&g_v[gi];
    }
    __syncthreads();   // Q staged

    for (int kt = 0; kt <= qt; kt++) {
        // stage prefetched K/V (float4 STS, natural [kv][d])
#pragma unroll
        for (int i = 0; i < 8; i++) {
            int f  = tid + i * 128;
            int r  = f >> 4;
            int c4 = (f & 15) << 2;
            *(float4*)&Ks[r * KSTR + c4] =
                make_float4(tf32r(kreg[i].x), tf32r(kreg[i].y),
                            tf32r(kreg[i].z), tf32r(kreg[i].w));
            *(float4*)&Vs[r * QSTR + c4] =
                make_float4(tf32r(vreg[i].x), tf32r(vreg[i].y),
                            tf32r(vreg[i].z), tf32r(vreg[i].w));
        }
        __syncthreads();

        // prefetch next tile (LDG overlaps all compute below)
        if (kt < qt) {
            const int kn0 = (kt + 1) * 64;
#pragma unroll
            for (int i = 0; i < 8; i++) {
                int f  = tid + i * 128;
                int r  = f >> 4;
                int c4 = (f & 15) << 2;
                size_t gi = base + (size_t)(kn0 + r) * DM + c4;
                kreg[i] = *(const float4*)&g_k[gi];
                vreg[i] = *(const float4*)&g_v[gi];
            }
        }

        const int k0 = kt * 64;

        // S = Q @ K^T
        float s[8][4];
#pragma unroll
        for (int nt = 0; nt < 8; nt++)
#pragma unroll
            for (int c = 0; c < 4; c++) s[nt][c] = 0.f;

#pragma unroll
        for (int kk = 0; kk < 8; kk++) {
            const int ko = kk * 8;
            unsigned a[4];
            {
                float2 f0 = *(const float2*)&Qs[qrow * QSTR + ko + 2 * t];
                float2 f1 = *(const float2*)&Qs[(qrow + 8) * QSTR + ko + 2 * t];
                a[0] = f2u(f0.x);
                a[1] = f2u(f1.x);
                a[2] = f2u(f0.y);
                a[3] = f2u(f1.y);
            }
#pragma unroll
            for (int nt = 0; nt < 8; nt++) {
                unsigned bf[2];
                bf[0] = f2u(Ks[(nt * 8 + g) * KSTR + ko + t]);
                bf[1] = f2u(Ks[(nt * 8 + g) * KSTR + ko + t + 4]);
                mma8(s[nt], a, bf);
            }
        }

        // scale + causal mask
        const bool diag = (kt == qt);
        const int qr0 = q0 + qrow, qr1 = qr0 + 8;
#pragma unroll
        for (int nt = 0; nt < 8; nt++) {
            int kc0 = k0 + nt * 8 + 2 * t;
            int kc1 = kc0 + 1;
            s[nt][0] *= 0.125f;
            s[nt][1] *= 0.125f;
            s[nt][2] *= 0.125f;
            s[nt][3] *= 0.125f;
            if (diag) {
                if (kc0 > qr0) s[nt][0] = -1e30f;
                if (kc1 > qr0) s[nt][1] = -1e30f;
                if (kc0 > qr1) s[nt][2] = -1e30f;
                if (kc1 > qr1) s[nt][3] = -1e30f;
            }
        }

        // online softmax
        float rmax0 = -1e30f, rmax1 = -1e30f;
#pragma unroll
        for (int nt = 0; nt < 8; nt++) {
            rmax0 = fmaxf(rmax0, fmaxf(s[nt][0], s[nt][1]));
            rmax1 = fmaxf(rmax1, fmaxf(s[nt][2], s[nt][3]));
        }
        rmax0 = fmaxf(rmax0, __shfl_xor_sync(0xffffffffu, rmax0, 1));
        rmax0 = fmaxf(rmax0, __shfl_xor_sync(0xffffffffu, rmax0, 2));
        rmax1 = fmaxf(rmax1, __shfl_xor_sync(0xffffffffu, rmax1, 1));
        rmax1 = fmaxf(rmax1, __shfl_xor_sync(0xffffffffu, rmax1, 2));

        float mn0 = fmaxf(m[0], rmax0);
        float mn1 = fmaxf(m[1], rmax1);
        float al0 = __expf(m[0] - mn0);
        float al1 = __expf(m[1] - mn1);
        float sum0 = 0.f, sum1 = 0.f;
#pragma unroll
        for (int nt = 0; nt < 8; nt++) {
            s[nt][0] = __expf(s[nt][0] - mn0);
            s[nt][1] = __expf(s[nt][1] - mn0);
            s[nt][2] = __expf(s[nt][2] - mn1);
            s[nt][3] = __expf(s[nt][3] - mn1);
            sum0 += s[nt][0] + s[nt][1];
            sum1 += s[nt][2] + s[nt][3];
        }
        sum0 += __shfl_xor_sync(0xffffffffu, sum0, 1);
        sum0 += __shfl_xor_sync(0xffffffffu, sum0, 2);
        sum1 += __shfl_xor_sync(0xffffffffu, sum1, 1);
        sum1 += __shfl_xor_sync(0xffffffffu, sum1, 2);

        l[0] = l[0] * al0 + sum0;
        l[1] = l[1] * al1 + sum1;
        m[0] = mn0;
        m[1] = mn1;
#pragma unroll
        for (int dt = 0; dt < 8; dt++) {
            o[dt][0] *= al0;
            o[dt][1] *= al0;
            o[dt][2] *= al1;
            o[dt][3] *= al1;
        }

        // store P (tf32) to permuted shared layout; warp-private rows
#pragma unroll
        for (int nt = 0; nt < 8; nt++) {
            int cb = nt * 8;
            Ps[qrow * QSTR + cb + p0]           = tf32r(s[nt][0]);
            Ps[qrow * QSTR + cb + p0 + 2]       = tf32r(s[nt][1]);
            Ps[(qrow + 8) * QSTR + cb + p0]     = tf32r(s[nt][2]);
            Ps[(qrow + 8) * QSTR + cb + p0 + 2] = tf32r(s[nt][3]);
        }
        __syncwarp();

        // O += P @ V
#pragma unroll
        for (int kk = 0; kk < 8; kk++) {
            const int ko = kk * 8;
            unsigned a[4];
            {
                float2 f0 = *(const float2*)&Ps[qrow * QSTR + ko + 2 * t];
                float2 f1 = *(const float2*)&Ps[(qrow + 8) * QSTR + ko + 2 * t];
                a[0] = f2u(f0.x);
                a[1] = f2u(f1.x);
                a[2] = f2u(f0.y);
                a[3] = f2u(f1.y);
            }
#pragma unroll
            for (int dt = 0; dt < 8; dt++) {
                unsigned bf[2];
                bf[0] = f2u(Vs[(ko + t) * QSTR + dt * 8 + g]);
                bf[1] = f2u(Vs[(ko + t + 4) * QSTR + dt * 8 + g]);
                mma8(o[dt], a, bf);
            }
        }
        __syncthreads();   // Ks/Vs consumed; next iter may overwrite
    }

    // epilogue: normalize, write ctx [B,S,H*hd]
    const float inv0 = 1.f / l[0];
    const float inv1 = 1.f / l[1];
#pragma unroll
    for (int dt = 0; dt < 8; dt++) {
        int c = dt * 8 + 2 * t;
        size_t i0 = base + (size_t)(q0 + qrow) * DM + c;
        size_t i1 = base + (size_t)(q0 + qrow + 8) * DM + c;
        *(float2*)&g_ctx[i0] = make_float2(o[dt][0] * inv0, o[dt][1] * inv0);
        *(float2*)&g_ctx[i1] = make_float2(o[dt][2] * inv1, o[dt][3] * inv1);
    }
}

// ---------------------------------------------------------------------------
extern "C" void kernel_launch(void* const* d_in, const int* in_sizes, int n_in,
                              void* d_out, int out_size)
{
    const float* x  = (const float*)d_in[0];
    const float* Wq = (const float*)d_in[1];
    const float* Wk = (const float*)d_in[2];
    const float* Wv = (const float*)d_in[3];
    const float* Wo = (const float*)d_in[4];
    const float* bo = (const float*)d_in[5];
    float* out = (float*)d_out;

    dim3 gq(DM / 128, MROWS / 128, 3);
    qkv_kernel<<<gq, 256>>>(x, Wq, Wk, Wv);

    const int smem = 64 * (QSTR + KSTR + QSTR + QSTR) * sizeof(float); // 72704
    cudaFuncSetAttribute(attn_kernel,
                         cudaFuncAttributeMaxDynamicSharedMemorySize, smem);
    attn_kernel<<<dim3(SS / 64, NH, BB), 128, smem>>>();

    proj_kernel<<<dim3(DM / 128, MROWS / 128, 1), 256>>>(Wo, bo, out);
}

// round 8
// speedup vs baseline: 3.7501x; 1.0769x over previous
#include <cuda_runtime.h>
#include <cstdint>
#include <cstddef>

// Problem constants
#define BB 2
#define SS 2048
#define DM 1024
#define NH 16
#define HD 64
#define MROWS (BB*SS)          // 4096

// Scratch (device globals — no runtime allocation allowed)
__device__ float g_q[MROWS * DM];
__device__ float g_k[MROWS * DM];
__device__ float g_v[MROWS * DM];
__device__ float g_ctx[MROWS * DM];
__device__ float g_x[MROWS * DM];      // tf32-rounded x
__device__ float g_wq[DM * DM];        // tf32-rounded weights
__device__ float g_wk[DM * DM];
__device__ float g_wv[DM * DM];
__device__ float g_wo[DM * DM];

// ---------------------------------------------------------------------------
// Helpers
// ---------------------------------------------------------------------------
__device__ __forceinline__ float tf32r(float x)
{
    asm("cvt.rna.tf32.f32 %0, %0;" : "+f"(x));
    return x;
}
__device__ __forceinline__ unsigned f2u(float x) { return __float_as_uint(x); }

__device__ __forceinline__ uint32_t smem_u32(const void* p)
{
    uint32_t a;
    asm("{ .reg .u64 t; cvta.to.shared.u64 t, %1; cvt.u32.u64 %0, t; }"
        : "=r"(a) : "l"(p));
    return a;
}

#define CP_ASYNC16(dst_u32, src_ptr) \
    asm volatile("cp.async.cg.shared.global [%0], [%1], 16;" \
                 :: "r"(dst_u32), "l"(src_ptr) : "memory")
#define CP_COMMIT() asm volatile("cp.async.commit_group;" ::: "memory")
#define CP_WAIT0()  asm volatile("cp.async.wait_group 0;" ::: "memory")
#define CP_WAIT1()  asm volatile("cp.async.wait_group 1;" ::: "memory")

// C[m16,n8] += A[m16,k8] * B[k8,n8], tf32 inputs, f32 accum
__device__ __forceinline__ void mma8(float* c, const unsigned* a, const unsigned* b)
{
    asm volatile(
        "mma.sync.aligned.m16n8k8.row.col.f32.tf32.tf32.f32 "
        "{%0,%1,%2,%3}, {%4,%5,%6,%7}, {%8,%9}, {%0,%1,%2,%3};\n"
        : "+f"(c[0]), "+f"(c[1]), "+f"(c[2]), "+f"(c[3])
        : "r"(a[0]), "r"(a[1]), "r"(a[2]), "r"(a[3]), "r"(b[0]), "r"(b[1]));
}

// ---------------------------------------------------------------------------
// Pre-round: dst = tf32r(src), one float4 per thread
// ---------------------------------------------------------------------------
__global__ void round_kernel(const float* __restrict__ s,
                             float* __restrict__ d, int n4)
{
    int i = blockIdx.x * blockDim.x + threadIdx.x;
    if (i < n4) {
        float4 v = ((const float4*)s)[i];
        ((float4*)d)[i] = make_float4(tf32r(v.x), tf32r(v.y),
                                      tf32r(v.z), tf32r(v.w));
    }
}

// ---------------------------------------------------------------------------
// tf32 MMA GEMM with cp.async staging. Inputs are PRE-ROUNDED tf32.
// C[M,1024] = A[M,1024] @ W[1024,1024] (+bias, optional output rounding).
// 128x128 CTA tile, BK=16, 256 thr = 8 warps (2M x 4N), warp tile 64x32.
// As: [m][k] natural, stride 20 (scalar a-frag LDS, banks 20g+t distinct).
// Bs: [k][n] natural, stride 152 (banks 24t+8nt+g distinct).
// Double-buffered cp.async, commit/wait groups.
// ---------------------------------------------------------------------------
#define GBK 16
#define ASTR 20
#define BSTR 152
#define NIT (DM / GBK)

__device__ __forceinline__ void gemm_body(const float* __restrict__ A,
                                          const float* __restrict__ W,
                                          float* __restrict__ C,
                                          const float* __restrict__ bias,
                                          bool round_out)
{
    __shared__ float As[2][128 * ASTR];   // 20480 B
    __shared__ float Bs[2][GBK * BSTR];   // 19456 B

    const int tid  = threadIdx.x;
    const int wid  = tid >> 5;
    const int lane = tid & 31;
    const int g    = lane >> 2;        // 0..7
    const int t    = lane & 3;         // 0..3
    const int wm   = (wid >> 2) * 64;  // 0 / 64
    const int wn   = (wid & 3) * 32;   // 0 / 32 / 64 / 96
    const int m0   = blockIdx.y * 128;
    const int n0   = blockIdx.x * 128;

    // cp.async chunk coordinates (2 chunks per tensor per thread)
    const int arow0 = tid >> 2;              // +0 / +... f=tid+256 -> row+64
    const int ac4   = (tid & 3) << 2;
    const int bk0   = tid >> 5;              // f=tid+256 -> k+8
    const int bc4   = (tid & 31) << 2;

    float acc[4][4][4];
#pragma unroll
    for (int mt = 0; mt < 4; mt++)
#pragma unroll
        for (int nt = 0; nt < 4; nt++)
#pragma unroll
            for (int c = 0; c < 4; c++) acc[mt][nt][c] = 0.f;

    // prologue: issue tile 0 into buffer 0
    {
        CP_ASYNC16(smem_u32(&As[0][arow0 * ASTR + ac4]),
                   &A[(size_t)(m0 + arow0) * DM + ac4]);
        CP_ASYNC16(smem_u32(&As[0][(arow0 + 64) * ASTR + ac4]),
                   &A[(size_t)(m0 + arow0 + 64) * DM + ac4]);
        CP_ASYNC16(smem_u32(&Bs[0][bk0 * BSTR + bc4]),
                   &W[(size_t)bk0 * DM + n0 + bc4]);
        CP_ASYNC16(smem_u32(&Bs[0][(bk0 + 8) * BSTR + bc4]),
                   &W[(size_t)(bk0 + 8) * DM + n0 + bc4]);
        CP_COMMIT();
    }

    for (int it = 0; it < NIT; it++) {
        const int b = it & 1;
        const bool more = (it + 1) < NIT;
        if (more) {
            const int kn = (it + 1) * GBK;
            float* an = As[b ^ 1];
            float* bn = Bs[b ^ 1];
            CP_ASYNC16(smem_u32(&an[arow0 * ASTR + ac4]),
                       &A[(size_t)(m0 + arow0) * DM + kn + ac4]);
            CP_ASYNC16(smem_u32(&an[(arow0 + 64) * ASTR + ac4]),
                       &A[(size_t)(m0 + arow0 + 64) * DM + kn + ac4]);
            CP_ASYNC16(smem_u32(&bn[bk0 * BSTR + bc4]),
                       &W[(size_t)(kn + bk0) * DM + n0 + bc4]);
            CP_ASYNC16(smem_u32(&bn[(bk0 + 8) * BSTR + bc4]),
                       &W[(size_t)(kn + bk0 + 8) * DM + n0 + bc4]);
            CP_COMMIT();
            CP_WAIT1();
        } else {
            CP_WAIT0();
        }
        __syncthreads();

        const float* __restrict__ as = As[b];
        const float* __restrict__ bs = Bs[b];
#pragma unroll
        for (int ks = 0; ks < 2; ks++) {
            const int ko = ks * 8;
            unsigned a[4][4], bfr[4][2];
#pragma unroll
            for (int mt = 0; mt < 4; mt++) {
                int r = wm + mt * 16 + g;
                a[mt][0] = f2u(as[r * ASTR + ko + t]);
                a[mt][1] = f2u(as[(r + 8) * ASTR + ko + t]);
                a[mt][2] = f2u(as[r * ASTR + ko + t + 4]);
                a[mt][3] = f2u(as[(r + 8) * ASTR + ko + t + 4]);
            }
#pragma unroll
            for (int nt = 0; nt < 4; nt++) {
                int n = wn + nt * 8 + g;
                bfr[nt][0] = f2u(bs[(ko + t) * BSTR + n]);
                bfr[nt][1] = f2u(bs[(ko + t + 4) * BSTR + n]);
            }
#pragma unroll
            for (int mt = 0; mt < 4; mt++)
#pragma unroll
                for (int nt = 0; nt < 4; nt++)
                    mma8(acc[mt][nt], a[mt], bfr[nt]);
        }
        __syncthreads();
    }

    // epilogue
#pragma unroll
    for (int mt = 0; mt < 4; mt++) {
        int r0 = m0 + wm + mt * 16 + g;
#pragma unroll
        for (int nt = 0; nt < 4; nt++) {
            int c0 = n0 + wn + nt * 8 + 2 * t;
            float v0 = acc[mt][nt][0], v1 = acc[mt][nt][1];
            float v2 = acc[mt][nt][2], v3 = acc[mt][nt][3];
            if (bias) {
                v0 += bias[c0];
                v1 += bias[c0 + 1];
                v2 += bias[c0];
                v3 += bias[c0 + 1];
            }
            if (round_out) {
                v0 = tf32r(v0); v1 = tf32r(v1);
                v2 = tf32r(v2); v3 = tf32r(v3);
            }
            *(float2*)&C[(size_t)r0 * DM + c0]       = make_float2(v0, v1);
            *(float2*)&C[(size_t)(r0 + 8) * DM + c0] = make_float2(v2, v3);
        }
    }
}

__global__ void __launch_bounds__(256, 2)
qkv_kernel()
{
    const float* W;
    float* Out;
    if (blockIdx.z == 0)      { W = g_wq; Out = g_q; }
    else if (blockIdx.z == 1) { W = g_wk; Out = g_k; }
    else                      { W = g_wv; Out = g_v; }
    gemm_body(g_x, W, Out, nullptr, true);   // outputs pre-rounded for attn
}

__global__ void __launch_bounds__(256, 2)
proj_kernel(const float* __restrict__ bo, float* __restrict__ out)
{
    gemm_body(g_ctx, g_wo, out, bo, false);
}

// ---------------------------------------------------------------------------
// Flash attention, tf32 mma.sync, cp.async staging (inputs pre-rounded).
// Block = (64 q rows, head, batch), 128 thr = 4 warps, warp = 16 q rows.
// Qs: [q][d] natural stride 68 (scalar a-frags, banks 4g+t distinct).
// Ps: [q][perm k] stride 72 (float2 a-frags) — written from registers.
// K:  [kv][d] stride 68 x2 bufs.  V: [kv][d] stride 72 x2 bufs.
// ---------------------------------------------------------------------------
#define QSTRA 68
#define PSTR 72
#define KSTR 68
#define VSTR 72
#define OFF_Q 0
#define OFF_P (64 * QSTRA)                 // 4352
#define OFF_K0 (OFF_P + 64 * PSTR)         // 8960
#define OFF_V0 (OFF_K0 + 64 * KSTR)        // 13312
#define OFF_K1 (OFF_V0 + 64 * VSTR)        // 17920
#define OFF_V1 (OFF_K1 + 64 * KSTR)        // 22272
#define ATTN_SMEM ((OFF_V1 + 64 * VSTR) * 4)   // 107520 B

__global__ void __launch_bounds__(128, 2) attn_kernel()
{
    extern __shared__ float sm[];
    float* Qs = sm + OFF_Q;
    float* Ps = sm + OFF_P;

    const int qt   = blockIdx.x;
    const int h    = blockIdx.y;
    const int b    = blockIdx.z;
    const int q0   = qt * 64;
    const int tid  = threadIdx.x;
    const int wid  = tid >> 5;
    const int lane = tid & 31;
    const int g    = lane >> 2;
    const int t    = lane & 3;
    const size_t base = (size_t)b * SS * DM + (size_t)h * HD;

    // prologue group: Q + K/V tile 0 -> buffer 0
#pragma unroll
    for (int i = 0; i < 8; i++) {
        int f  = tid + i * 128;
        int r  = f >> 4;
        int c4 = (f & 15) << 2;
        CP_ASYNC16(smem_u32(&Qs[r * QSTRA + c4]),
                   &g_q[base + (size_t)(q0 + r) * DM + c4]);
        CP_ASYNC16(smem_u32(&sm[OFF_K0 + r * KSTR + c4]),
                   &g_k[base + (size_t)r * DM + c4]);
        CP_ASYNC16(smem_u32(&sm[OFF_V0 + r * VSTR + c4]),
                   &g_v[base + (size_t)r * DM + c4]);
    }
    CP_COMMIT();

    float m[2] = {-1e30f, -1e30f};
    float l[2] = {0.f, 0.f};
    float o[8][4];
#pragma unroll
    for (int dt = 0; dt < 8; dt++)
#pragma unroll
        for (int c = 0; c < 4; c++) o[dt][c] = 0.f;

    const int qrow = wid * 16 + g;
    const int p0 = ((t & 1) << 2) | (t >> 1);

    for (int kt = 0; kt <= qt; kt++) {
        const int bsel = kt & 1;
        if (kt < qt) {
            const int kn0 = (kt + 1) * 64;
            const int offk = bsel ? OFF_K0 : OFF_K1;
            const int offv = bsel ? OFF_V0 : OFF_V1;
#pragma unroll
            for (int i = 0; i < 8; i++) {
                int f  = tid + i * 128;
                int r  = f >> 4;
                int c4 = (f & 15) << 2;
                CP_ASYNC16(smem_u32(&sm[offk + r * KSTR + c4]),
                           &g_k[base + (size_t)(kn0 + r) * DM + c4]);
                CP_ASYNC16(smem_u32(&sm[offv + r * VSTR + c4]),
                           &g_v[base + (size_t)(kn0 + r) * DM + c4]);
            }
            CP_COMMIT();
            CP_WAIT1();
        } else {
            CP_WAIT0();
        }
        __syncthreads();

        const float* Ks = sm + (bsel ? OFF_K1 : OFF_K0);
        const float* Vs = sm + (bsel ? OFF_V1 : OFF_V0);
        const int k0 = kt * 64;

        // S = Q @ K^T (m16 x n64 per warp)
        float s[8][4];
#pragma unroll
        for (int nt = 0; nt < 8; nt++)
#pragma unroll
            for (int c = 0; c < 4; c++) s[nt][c] = 0.f;

#pragma unroll
        for (int kk = 0; kk < 8; kk++) {
            const int ko = kk * 8;
            unsigned a[4];
            a[0] = f2u(Qs[qrow * QSTRA + ko + t]);
            a[1] = f2u(Qs[(qrow + 8) * QSTRA + ko + t]);
            a[2] = f2u(Qs[qrow * QSTRA + ko + t + 4]);
            a[3] = f2u(Qs[(qrow + 8) * QSTRA + ko + t + 4]);
#pragma unroll
            for (int nt = 0; nt < 8; nt++) {
                unsigned bf[2];
                bf[0] = f2u(Ks[(nt * 8 + g) * KSTR + ko + t]);
                bf[1] = f2u(Ks[(nt * 8 + g) * KSTR + ko + t + 4]);
                mma8(s[nt], a, bf);
            }
        }

        // scale + causal mask
        const bool diag = (kt == qt);
        const int qr0 = q0 + qrow, qr1 = qr0 + 8;
#pragma unroll
        for (int nt = 0; nt < 8; nt++) {
            int kc0 = k0 + nt * 8 + 2 * t;
            int kc1 = kc0 + 1;
            s[nt][0] *= 0.125f;
            s[nt][1] *= 0.125f;
            s[nt][2] *= 0.125f;
            s[nt][3] *= 0.125f;
            if (diag) {
                if (kc0 > qr0) s[nt][0] = -1e30f;
                if (kc1 > qr0) s[nt][1] = -1e30f;
                if (kc0 > qr1) s[nt][2] = -1e30f;
                if (kc1 > qr1) s[nt][3] = -1e30f;
            }
        }

        // online softmax
        float rmax0 = -1e30f, rmax1 = -1e30f;
#pragma unroll
        for (int nt = 0; nt < 8; nt++) {
            rmax0 = fmaxf(rmax0, fmaxf(s[nt][0], s[nt][1]));
            rmax1 = fmaxf(rmax1, fmaxf(s[nt][2], s[nt][3]));
        }
        rmax0 = fmaxf(rmax0, __shfl_xor_sync(0xffffffffu, rmax0, 1));
        rmax0 = fmaxf(rmax0, __shfl_xor_sync(0xffffffffu, rmax0, 2));
        rmax1 = fmaxf(rmax1, __shfl_xor_sync(0xffffffffu, rmax1, 1));
        rmax1 = fmaxf(rmax1, __shfl_xor_sync(0xffffffffu, rmax1, 2));

        float mn0 = fmaxf(m[0], rmax0);
        float mn1 = fmaxf(m[1], rmax1);
        float al0 = __expf(m[0] - mn0);
        float al1 = __expf(m[1] - mn1);
        float sum0 = 0.f, sum1 = 0.f;
#pragma unroll
        for (int nt = 0; nt < 8; nt++) {
            s[nt][0] = __expf(s[nt][0] - mn0);
            s[nt][1] = __expf(s[nt][1] - mn0);
            s[nt][2] = __expf(s[nt][2] - mn1);
            s[nt][3] = __expf(s[nt][3] - mn1);
            sum0 += s[nt][0] + s[nt][1];
            sum1 += s[nt][2] + s[nt][3];
        }
        sum0 += __shfl_xor_sync(0xffffffffu, sum0, 1);
        sum0 += __shfl_xor_sync(0xffffffffu, sum0, 2);
        sum1 += __shfl_xor_sync(0xffffffffu, sum1, 1);
        sum1 += __shfl_xor_sync(0xffffffffu, sum1, 2);

        l[0] = l[0] * al0 + sum0;
        l[1] = l[1] * al1 + sum1;
        m[0] = mn0;
        m[1] = mn1;
#pragma unroll
        for (int dt = 0; dt < 8; dt++) {
            o[dt][0] *= al0;
            o[dt][1] *= al0;
            o[dt][2] *= al1;
            o[dt][3] *= al1;
        }

        // store P (tf32) to permuted shared layout; warp-private rows
#pragma unroll
        for (int nt = 0; nt < 8; nt++) {
            int cb = nt * 8;
            Ps[qrow * PSTR + cb + p0]           = tf32r(s[nt][0]);
            Ps[qrow * PSTR + cb + p0 + 2]       = tf32r(s[nt][1]);
            Ps[(qrow + 8) * PSTR + cb + p0]     = tf32r(s[nt][2]);
            Ps[(qrow + 8) * PSTR + cb + p0 + 2] = tf32r(s[nt][3]);
        }
        __syncwarp();

        // O += P @ V
#pragma unroll
        for (int kk = 0; kk < 8; kk++) {
            const int ko = kk * 8;
            unsigned a[4];
            {
                float2 f0 = *(const float2*)&Ps[qrow * PSTR + ko + 2 * t];
                float2 f1 = *(const float2*)&Ps[(qrow + 8) * PSTR + ko + 2 * t];
                a[0] = f2u(f0.x);
                a[1] = f2u(f1.x);
                a[2] = f2u(f0.y);
                a[3] = f2u(f1.y);
            }
#pragma unroll
            for (int dt = 0; dt < 8; dt++) {
                unsigned bf[2];
                bf[0] = f2u(Vs[(ko + t) * VSTR + dt * 8 + g]);
                bf[1] = f2u(Vs[(ko + t + 4) * VSTR + dt * 8 + g]);
                mma8(o[dt], a, bf);
            }
        }
        __syncthreads();   // all reads of this buffer done before reuse
    }

    // epilogue: normalize, round for proj staging, write ctx [B,S,H*hd]
    const float inv0 = 1.f / l[0];
    const float inv1 = 1.f / l[1];
#pragma unroll
    for (int dt = 0; dt < 8; dt++) {
        int c = dt * 8 + 2 * t;
        size_t i0 = base + (size_t)(q0 + qrow) * DM + c;
        size_t i1 = base + (size_t)(q0 + qrow + 8) * DM + c;
        *(float2*)&g_ctx[i0] = make_float2(tf32r(o[dt][0] * inv0),
                                           tf32r(o[dt][1] * inv0));
        *(float2*)&g_ctx[i1] = make_float2(tf32r(o[dt][2] * inv1),
                                           tf32r(o[dt][3] * inv1));
    }
}

// ---------------------------------------------------------------------------
extern "C" void kernel_launch(void* const* d_in, const int* in_sizes, int n_in,
                              void* d_out, int out_size)
{
    const float* x  = (const float*)d_in[0];
    const float* Wq = (const float*)d_in[1];
    const float* Wk = (const float*)d_in[2];
    const float* Wv = (const float*)d_in[3];
    const float* Wo = (const float*)d_in[4];
    const float* bo = (const float*)d_in[5];
    float* out = (float*)d_out;

    float* dxp;  cudaGetSymbolAddress((void**)&dxp,  g_x);
    float* dwq;  cudaGetSymbolAddress((void**)&dwq,  g_wq);
    float* dwk;  cudaGetSymbolAddress((void**)&dwk,  g_wk);
    float* dwv;  cudaGetSymbolAddress((void**)&dwv,  g_wv);
    float* dwo;  cudaGetSymbolAddress((void**)&dwo,  g_wo);

    const int n4x = MROWS * DM / 4;   // 1048576
    const int n4w = DM * DM / 4;      // 262144
    round_kernel<<<n4x / 256, 256>>>(x,  dxp, n4x);
    round_kernel<<<n4w / 256, 256>>>(Wq, dwq, n4w);
    round_kernel<<<n4w / 256, 256>>>(Wk, dwk, n4w);
    round_kernel<<<n4w / 256, 256>>>(Wv, dwv, n4w);
    round_kernel<<<n4w / 256, 256>>>(Wo, dwo, n4w);

    dim3 gq(DM / 128, MROWS / 128, 3);
    qkv_kernel<<<gq, 256>>>();

    cudaFuncSetAttribute(attn_kernel,
                         cudaFuncAttributeMaxDynamicSharedMemorySize, ATTN_SMEM);
    attn_kernel<<<dim3(SS / 64, NH, BB), 128, ATTN_SMEM>>>();

    proj_kernel<<<dim3(DM / 128, MROWS / 128, 1), 256>>>(bo, out);
}